// round 2
// baseline (speedup 1.0000x reference)
#include <cuda_runtime.h>

#define NPIX 128
#define LD   129          // padded row stride (float2) -> conflict-free column access
#define NT   512
#define PI_F 3.14159265358979323846f

__device__ __forceinline__ float2 cmul(float2 a, float2 b) {
    return make_float2(fmaf(a.x, b.x, -a.y * b.y), fmaf(a.x, b.y, a.y * b.x));
}
__device__ __forceinline__ int brev7(int k) { return (int)(__brev((unsigned)k) >> 25); }

// One 1-D FFT pass over all 128 lines (rows==1: transform along x; rows==0: along y).
// Forward: DIF, natural in -> bit-reversed out. Inverse: conj DIT, bit-reversed in -> natural out
// (unscaled; the 1/128 per axis is folded into the propagator table PF).
__device__ __noinline__ void fft_pass(float2* F, const float2* TW, int rows, int inverse)
{
    if (!inverse) {
        #pragma unroll
        for (int s = 0; s < 7; ++s) {
            const int shift = 6 - s;              // log2(half)
            #pragma unroll 4
            for (int b = threadIdx.x; b < 8192; b += NT) {
                int j = b >> 7;                   // butterfly index within line [0,64)
                int l = b & 127;                  // line index
                int p = j & ((1 << shift) - 1);
                int g = j >> shift;
                int i0 = (g << (shift + 1)) + p;
                int i1 = i0 + (1 << shift);
                int a0 = rows ? (l * LD + i0) : (i0 * LD + l);
                int a1 = rows ? (l * LD + i1) : (i1 * LD + l);
                float2 a = F[a0];
                float2 c = F[a1];
                float2 w = TW[p << s];
                float2 d = make_float2(a.x - c.x, a.y - c.y);
                F[a0] = make_float2(a.x + c.x, a.y + c.y);
                F[a1] = cmul(d, w);
            }
            __syncthreads();
        }
    } else {
        #pragma unroll
        for (int s = 6; s >= 0; --s) {
            const int shift = 6 - s;
            #pragma unroll 4
            for (int b = threadIdx.x; b < 8192; b += NT) {
                int j = b >> 7;
                int l = b & 127;
                int p = j & ((1 << shift) - 1);
                int g = j >> shift;
                int i0 = (g << (shift + 1)) + p;
                int i1 = i0 + (1 << shift);
                int a0 = rows ? (l * LD + i0) : (i0 * LD + l);
                int a1 = rows ? (l * LD + i1) : (i1 * LD + l);
                float2 a = F[a0];
                float2 w = TW[p << s];
                w.y = -w.y;                       // conjugate twiddle for inverse
                float2 c = cmul(F[a1], w);
                F[a0] = make_float2(a.x + c.x, a.y + c.y);
                F[a1] = make_float2(a.x - c.x, a.y - c.y);
            }
            __syncthreads();
        }
    }
}

__global__ void __launch_bounds__(NT, 1)
ms_kernel(const float* __restrict__ pr, const float* __restrict__ pim,
          const float* __restrict__ obr, const float* __restrict__ obi,
          const int* __restrict__ posn, float* __restrict__ out)
{
    extern __shared__ float2 sm[];
    float2* F  = sm;                  // [128][129] field
    float2* TW = sm + NPIX * LD;      // 64 forward twiddles W_128^k
    float2* PF = TW + 64;             // 128 propagator axis factors, BIT-REVERSED index, * (1/128)

    const int tid = threadIdx.x;
    const int n = blockIdx.x >> 2;    // scan position
    const int m = blockIdx.x & 3;     // probe mode
    const int py0 = posn[2 * n];
    const int px0 = posn[2 * n + 1];

    // --- tables ---
    if (tid < 64) {
        float ang = -2.0f * PI_F * (float)tid * (1.0f / 128.0f);
        float sv, cv; sincosf(ang, &sv, &cv);
        TW[tid] = make_float2(cv, sv);
    } else if (tid < 192) {
        int k = tid - 64;
        int kk = brev7(k);
        float f = (float)(kk < 64 ? kk : kk - 128) * (1.0f / (128.0f * 0.2f)); // fftfreq
        float phase = -PI_F * 0.025f * 2.0f * f * f;   // -pi * wl * dz * k^2  (per axis)
        float sv, cv; sincosf(phase, &sv, &cv);
        PF[k] = make_float2(cv * (1.0f / 128.0f), sv * (1.0f / 128.0f)); // fold ifft 1/N scale
    }

    // --- field = probe[m] * patch(slice 0) ---
    const float* prm = pr  + m * (NPIX * NPIX);
    const float* pmm = pim + m * (NPIX * NPIX);
    {
        const int base = py0 * 512 + px0;  // slice 0
        for (int e = tid; e < NPIX * NPIX; e += NT) {
            int y = e >> 7, x = e & 127;
            int o = base + y * 512 + x;
            float2 P = make_float2(prm[e], pmm[e]);
            float2 T = make_float2(obr[o], obi[o]);
            F[y * LD + x] = cmul(P, T);
        }
    }
    __syncthreads();

    // --- multislice: [fft2 -> *prop -> ifft2 -> *patch] for slices 1..7 ---
    for (int s = 1; s < 8; ++s) {
        fft_pass(F, TW, 1, 0);   // rows forward
        fft_pass(F, TW, 0, 0);   // cols forward  -> bit-reversed in both dims
        for (int e = tid; e < NPIX * NPIX; e += NT) {
            int u = e >> 7, v = e & 127;
            float2 w = cmul(PF[u], PF[v]);       // propagator in bit-reversed space
            F[u * LD + v] = cmul(F[u * LD + v], w);
        }
        __syncthreads();
        fft_pass(F, TW, 0, 1);   // cols inverse
        fft_pass(F, TW, 1, 1);   // rows inverse -> natural order
        const int base = (s * 512 + py0) * 512 + px0;
        for (int e = tid; e < NPIX * NPIX; e += NT) {
            int y = e >> 7, x = e & 127;
            int o = base + y * 512 + x;
            float2 T = make_float2(obr[o], obi[o]);
            F[y * LD + x] = cmul(F[y * LD + x], T);
        }
        __syncthreads();
    }

    // --- final fft2 (leave bit-reversed; undo in the output indexing) ---
    fft_pass(F, TW, 1, 0);
    fft_pass(F, TW, 0, 0);

    // out[n,y,x] += |X[(y+64)%128][(x+64)%128]|^2, X[k] lives at F[brev7(k)]
    float* outn = out + n * (NPIX * NPIX);
    for (int e = tid; e < NPIX * NPIX; e += NT) {
        int y = e >> 7, x = e & 127;
        int u = brev7((y + 64) & 127);
        int v = brev7((x + 64) & 127);
        float2 a = F[u * LD + v];
        atomicAdd(&outn[e], fmaf(a.x, a.x, a.y * a.y));
    }
}

extern "C" void kernel_launch(void* const* d_in, const int* in_sizes, int n_in,
                              void* d_out, int out_size)
{
    const float* pr  = (const float*)d_in[0];  // probe_real (4,128,128)
    const float* pim = (const float*)d_in[1];  // probe_imag
    const float* obr = (const float*)d_in[2];  // obj_real   (8,512,512)
    const float* obi = (const float*)d_in[3];  // obj_imag
    const int*   pos = (const int*)d_in[4];    // positions  (512,2)
    float* out = (float*)d_out;                // (512,128,128) float32

    cudaMemsetAsync(out, 0, (size_t)out_size * sizeof(float), 0);

    size_t smem = (size_t)(NPIX * LD + 64 + NPIX) * sizeof(float2);  // 133,632 B
    cudaFuncSetAttribute(ms_kernel, cudaFuncAttributeMaxDynamicSharedMemorySize, (int)smem);
    ms_kernel<<<512 * 4, NT, smem>>>(pr, pim, obr, obi, pos, out);
}

// round 5
// speedup vs baseline: 2.3561x; 2.3561x over previous
#include <cuda_runtime.h>

#define NPIX 128
#define LD   129          // padded row stride (float2) -> conflict-free column access
#define NT   512
#define PI_F 3.14159265358979323846f
#define CC   0.70710678118654752440f   // cos(pi/4)

__device__ __forceinline__ float2 cadd(float2 a, float2 b){return make_float2(a.x+b.x, a.y+b.y);}
__device__ __forceinline__ float2 csub(float2 a, float2 b){return make_float2(a.x-b.x, a.y-b.y);}
__device__ __forceinline__ float2 cmul(float2 a, float2 b){
    return make_float2(fmaf(a.x,b.x,-a.y*b.y), fmaf(a.x,b.y,a.y*b.x));
}
__device__ __forceinline__ float2 mul_mi(float2 a){return make_float2(a.y,-a.x);}   // *(-i)
__device__ __forceinline__ float2 mul_pi(float2 a){return make_float2(-a.y,a.x);}   // *(+i)
__device__ __forceinline__ float2 mulW16 (float2 a){return make_float2(CC*(a.x+a.y),  CC*(a.y-a.x));} // *e^{-i pi/4}
__device__ __forceinline__ float2 mulW48 (float2 a){return make_float2(CC*(a.y-a.x), -CC*(a.x+a.y));} // *e^{-3i pi/4}
__device__ __forceinline__ float2 mulW16c(float2 a){return make_float2(CC*(a.x-a.y),  CC*(a.x+a.y));} // *e^{+i pi/4}
__device__ __forceinline__ float2 mulW48c(float2 a){return make_float2(-CC*(a.x+a.y), CC*(a.x-a.y));} // *e^{+3i pi/4}
__device__ __forceinline__ int brev7(int k){return (int)(__brev((unsigned)k) >> 25);}

// Forward DIF radix-4 (fuses radix-2 stages s, s+1). w2 = w1*(-i), w3 = w1^2.
__device__ __forceinline__ void bf4f(float2& a0, float2& a1, float2& a2, float2& a3, float2 w1){
    float2 w2 = mul_mi(w1);
    float2 w3 = cmul(w1, w1);
    float2 b0 = cadd(a0, a2);
    float2 b2 = cmul(csub(a0, a2), w1);
    float2 b1 = cadd(a1, a3);
    float2 b3 = cmul(csub(a1, a3), w2);
    a0 = cadd(b0, b1);
    a1 = cmul(csub(b0, b1), w3);
    a2 = cadd(b2, b3);
    a3 = cmul(csub(b2, b3), w3);
}

// Inverse conj-DIT radix-4 (fuses radix-2 stages shift=t, t+1). cw1 = cw2^2, cw3 = i*cw2.
__device__ __forceinline__ void bf4i(float2& a0, float2& a1, float2& a2, float2& a3, float2 cw2){
    float2 cw1 = cmul(cw2, cw2);
    float2 cw3 = mul_pi(cw2);
    float2 t;
    t = cmul(a1, cw1); float2 b0 = cadd(a0, t), b1 = csub(a0, t);
    t = cmul(a3, cw1); float2 b2 = cadd(a2, t), b3 = csub(a2, t);
    t = cmul(b2, cw2); a0 = cadd(b0, t); a2 = csub(b0, t);
    t = cmul(b3, cw3); a1 = cadd(b1, t); a3 = csub(b1, t);
}

// Forward DIF radix-8 = radix-2 stages s=4,5,6 on 8 contiguous points. Constant twiddles.
__device__ __forceinline__ void bf8f(float2 x[8]){
    float2 y0=cadd(x[0],x[4]), y4=csub(x[0],x[4]);
    float2 y1=cadd(x[1],x[5]), y5=mulW16(csub(x[1],x[5]));
    float2 y2=cadd(x[2],x[6]), y6=mul_mi(csub(x[2],x[6]));
    float2 y3=cadd(x[3],x[7]), y7=mulW48(csub(x[3],x[7]));
    float2 z0=cadd(y0,y2), z2=csub(y0,y2);
    float2 z1=cadd(y1,y3), z3=mul_mi(csub(y1,y3));
    float2 z4=cadd(y4,y6), z6=csub(y4,y6);
    float2 z5=cadd(y5,y7), z7=mul_mi(csub(y5,y7));
    x[0]=cadd(z0,z1); x[1]=csub(z0,z1);
    x[2]=cadd(z2,z3); x[3]=csub(z2,z3);
    x[4]=cadd(z4,z5); x[5]=csub(z4,z5);
    x[6]=cadd(z6,z7); x[7]=csub(z6,z7);
}

// Inverse conj-DIT radix-8 = radix-2 stages shift=0,1,2 on 8 contiguous points.
__device__ __forceinline__ void bf8i(float2 x[8]){
    float2 y0=cadd(x[0],x[1]), y1=csub(x[0],x[1]);
    float2 y2=cadd(x[2],x[3]), y3=csub(x[2],x[3]);
    float2 y4=cadd(x[4],x[5]), y5=csub(x[4],x[5]);
    float2 y6=cadd(x[6],x[7]), y7=csub(x[6],x[7]);
    float2 t;
    float2 z0=cadd(y0,y2), z2=csub(y0,y2);
    t = mul_pi(y3);
    float2 z1=cadd(y1,t), z3=csub(y1,t);
    float2 z4=cadd(y4,y6), z6=csub(y4,y6);
    t = mul_pi(y7);
    float2 z5=cadd(y5,t), z7=csub(y5,t);
    x[0]=cadd(z0,z4); x[4]=csub(z0,z4);
    t = mulW16c(z5); x[1]=cadd(z1,t); x[5]=csub(z1,t);
    t = mul_pi(z6);  x[2]=cadd(z2,t); x[6]=csub(z2,t);
    t = mulW48c(z7); x[3]=cadd(z3,t); x[7]=csub(z3,t);
}

// ---------------- sweeps (each ends with __syncthreads) ----------------

// Generic forward radix-4 sweep over all 128 lines. S in {0,2}. ROWS: along x vs along y.
template<int S, bool ROWS>
__device__ __noinline__ void sweep_r4f(float2* F, const float2* TW){
    constexpr int q = 1 << (5 - S);
    #pragma unroll 2
    for (int b = threadIdx.x; b < 4096; b += NT) {
        int j = b >> 7, l = b & 127;
        int p0 = j & (q - 1);
        int i = ((j >> (5 - S)) << (7 - S)) + p0;
        int base = ROWS ? (l * LD + i) : (i * LD + l);
        int st   = ROWS ? q : q * LD;
        float2 a0 = F[base], a1 = F[base+st], a2 = F[base+2*st], a3 = F[base+3*st];
        bf4f(a0, a1, a2, a3, TW[p0 << S]);
        F[base] = a0; F[base+st] = a1; F[base+2*st] = a2; F[base+3*st] = a3;
    }
    __syncthreads();
}

// Forward radix-4 S=0 along rows, FUSED with pointwise multiply by obj patch
// (and by probe on the first round, reading the field from global instead of SMEM).
// Thread mapping (j = tid&31, l = tid>>5) keeps global loads coalesced and SMEM stride-1.
template<bool FIRST>
__device__ __noinline__ void sweep_r4f_rows0_fused(
    float2* F, const float2* TW,
    const float* __restrict__ obr, const float* __restrict__ obi, int obase,
    const float* __restrict__ prm, const float* __restrict__ pim)
{
    #pragma unroll 2
    for (int b = threadIdx.x; b < 4096; b += NT) {
        int j = b & 31, l = b >> 5;
        int rowS = l * LD;
        int rowG = obase + l * 512;
        float2 a[4];
        #pragma unroll
        for (int k = 0; k < 4; ++k) {
            int x = j + 32 * k;
            float2 T = make_float2(obr[rowG + x], obi[rowG + x]);
            float2 v;
            if (FIRST) v = make_float2(prm[(l << 7) + x], pim[(l << 7) + x]);
            else       v = F[rowS + x];
            a[k] = cmul(v, T);
        }
        bf4f(a[0], a[1], a[2], a[3], TW[j]);
        F[rowS + j] = a[0]; F[rowS + j + 32] = a[1];
        F[rowS + j + 64] = a[2]; F[rowS + j + 96] = a[3];
    }
    __syncthreads();
}

// Forward radix-8 sweep (stages 4,5,6). Optionally fuse propagator multiply on write
// (PF stored in bit-reversed index order, carries the 1/128-per-axis ifft scale).
template<bool ROWS, bool PROP>
__device__ __noinline__ void sweep_r8f(float2* F, const float2* PF){
    #pragma unroll 1
    for (int b = threadIdx.x; b < 2048; b += NT) {
        int g = b >> 7, l = b & 127;
        int i0 = g << 3;
        float2 x[8];
        #pragma unroll
        for (int k = 0; k < 8; ++k)
            x[k] = ROWS ? F[l * LD + i0 + k] : F[(i0 + k) * LD + l];
        bf8f(x);
        if (PROP) {
            float2 pl = PF[l];
            #pragma unroll
            for (int k = 0; k < 8; ++k)
                x[k] = cmul(x[k], cmul(PF[i0 + k], pl));
        }
        #pragma unroll
        for (int k = 0; k < 8; ++k)
            (ROWS ? F[l * LD + i0 + k] : F[(i0 + k) * LD + l]) = x[k];
    }
    __syncthreads();
}

// Inverse radix-8 sweep (stages shift=0,1,2) — first step of each inverse 1-D FFT.
template<bool ROWS>
__device__ __noinline__ void sweep_r8i(float2* F){
    #pragma unroll 1
    for (int b = threadIdx.x; b < 2048; b += NT) {
        int g = b >> 7, l = b & 127;
        int i0 = g << 3;
        float2 x[8];
        #pragma unroll
        for (int k = 0; k < 8; ++k)
            x[k] = ROWS ? F[l * LD + i0 + k] : F[(i0 + k) * LD + l];
        bf8i(x);
        #pragma unroll
        for (int k = 0; k < 8; ++k)
            (ROWS ? F[l * LD + i0 + k] : F[(i0 + k) * LD + l]) = x[k];
    }
    __syncthreads();
}

// Inverse radix-4 sweep (stages shift=T, T+1). T in {3,5}.
template<int T, bool ROWS>
__device__ __noinline__ void sweep_r4i(float2* F, const float2* TW){
    constexpr int h = 1 << T;
    #pragma unroll 2
    for (int b = threadIdx.x; b < 4096; b += NT) {
        int j = b >> 7, l = b & 127;
        int p0 = j & (h - 1);
        int i = ((j >> T) << (T + 2)) + p0;
        int base = ROWS ? (l * LD + i) : (i * LD + l);
        int st   = ROWS ? h : h * LD;
        float2 a0 = F[base], a1 = F[base+st], a2 = F[base+2*st], a3 = F[base+3*st];
        float2 w = TW[p0 << (5 - T)];
        bf4i(a0, a1, a2, a3, make_float2(w.x, -w.y));
        F[base] = a0; F[base+st] = a1; F[base+2*st] = a2; F[base+3*st] = a3;
    }
    __syncthreads();
}

__global__ void __launch_bounds__(NT, 1)
ms_kernel(const float* __restrict__ pr, const float* __restrict__ pim,
          const float* __restrict__ obr, const float* __restrict__ obi,
          const int* __restrict__ posn, float* __restrict__ out)
{
    extern __shared__ float2 sm[];
    float2* F  = sm;                  // [128][129] field
    float2* TW = sm + NPIX * LD;      // 64 forward twiddles W_128^k
    float2* PF = TW + 64;             // 128 propagator axis factors, bit-reversed, * (1/128)

    const int tid = threadIdx.x;
    const int n = blockIdx.x >> 2;    // scan position
    const int m = blockIdx.x & 3;     // probe mode
    const int py0 = posn[2 * n];
    const int px0 = posn[2 * n + 1];

    // --- tables ---
    if (tid < 64) {
        float ang = -2.0f * PI_F * (float)tid * (1.0f / 128.0f);
        float sv, cv; sincosf(ang, &sv, &cv);
        TW[tid] = make_float2(cv, sv);
    } else if (tid < 192) {
        int k = tid - 64;
        int kk = brev7(k);
        float f = (float)(kk < 64 ? kk : kk - 128) * (1.0f / (128.0f * 0.2f)); // fftfreq
        float phase = -PI_F * 0.025f * 2.0f * f * f;   // -pi*wl*dz*k^2 per axis
        float sv, cv; sincosf(phase, &sv, &cv);
        PF[k] = make_float2(cv * (1.0f / 128.0f), sv * (1.0f / 128.0f)); // fold ifft scale
    }
    __syncthreads();

    const float* prm = pr  + m * (NPIX * NPIX);
    const float* pmm = pim + m * (NPIX * NPIX);

    // 8 rounds: [*patch_s (fused)] fft2 ; rounds 0..6 additionally: [*prop (fused)] ifft2
    #pragma unroll 1
    for (int s = 0; s < 8; ++s) {
        const int obase = ((s << 9) + py0) * 512 + px0;   // slice s patch origin

        // forward rows: 3 sweeps (first fused with patch/probe multiply)
        if (s == 0) sweep_r4f_rows0_fused<true >(F, TW, obr, obi, obase, prm, pmm);
        else        sweep_r4f_rows0_fused<false>(F, TW, obr, obi, obase, prm, pmm);
        sweep_r4f<2, true>(F, TW);
        sweep_r8f<true, false>(F, PF);

        // forward cols: 3 sweeps (last fused with propagator, except final round)
        sweep_r4f<0, false>(F, TW);
        sweep_r4f<2, false>(F, TW);
        if (s < 7) {
            sweep_r8f<false, true>(F, PF);
            // inverse cols then inverse rows: 3 + 3 sweeps
            sweep_r8i<false>(F);
            sweep_r4i<3, false>(F, TW);
            sweep_r4i<5, false>(F, TW);
            sweep_r8i<true>(F);
            sweep_r4i<3, true>(F, TW);
            sweep_r4i<5, true>(F, TW);
        } else {
            sweep_r8f<false, false>(F, PF);
        }
    }

    // out[n,y,x] += |X[(y+64)%128][(x+64)%128]|^2 with X[k] at F[brev7(k)]
    float* outn = out + n * (NPIX * NPIX);
    for (int e = tid; e < NPIX * NPIX; e += NT) {
        int y = e >> 7, x = e & 127;
        int u = brev7((y + 64) & 127);
        int v = brev7((x + 64) & 127);
        float2 a = F[u * LD + v];
        atomicAdd(&outn[e], fmaf(a.x, a.x, a.y * a.y));
    }
}

extern "C" void kernel_launch(void* const* d_in, const int* in_sizes, int n_in,
                              void* d_out, int out_size)
{
    const float* pr  = (const float*)d_in[0];  // probe_real (4,128,128)
    const float* pim = (const float*)d_in[1];  // probe_imag
    const float* obr = (const float*)d_in[2];  // obj_real   (8,512,512)
    const float* obi = (const float*)d_in[3];  // obj_imag
    const int*   pos = (const int*)d_in[4];    // positions  (512,2)
    float* out = (float*)d_out;                // (512,128,128) float32

    cudaMemsetAsync(out, 0, (size_t)out_size * sizeof(float), 0);

    size_t smem = (size_t)(NPIX * LD + 64 + NPIX) * sizeof(float2);  // 133,632 B
    cudaFuncSetAttribute(ms_kernel, cudaFuncAttributeMaxDynamicSharedMemorySize, (int)smem);
    ms_kernel<<<512 * 4, NT, smem>>>(pr, pim, obr, obi, pos, out);
}

// round 6
// speedup vs baseline: 2.3574x; 1.0006x over previous
#include <cuda_runtime.h>

#define NPIX 128
#define LD   129          // padded row stride (float2) -> conflict-free column access
#define NT   512
#define PI_F 3.14159265358979323846f
#define CC   0.70710678118654752440f   // cos(pi/4)

__device__ __forceinline__ float2 cadd(float2 a, float2 b){return make_float2(a.x+b.x, a.y+b.y);}
__device__ __forceinline__ float2 csub(float2 a, float2 b){return make_float2(a.x-b.x, a.y-b.y);}
__device__ __forceinline__ float2 cmul(float2 a, float2 b){
    return make_float2(fmaf(a.x,b.x,-a.y*b.y), fmaf(a.x,b.y,a.y*b.x));
}
__device__ __forceinline__ float2 mul_mi(float2 a){return make_float2(a.y,-a.x);}   // *(-i)
__device__ __forceinline__ float2 mul_pi(float2 a){return make_float2(-a.y,a.x);}   // *(+i)
__device__ __forceinline__ float2 mulW16 (float2 a){return make_float2(CC*(a.x+a.y),  CC*(a.y-a.x));} // *e^{-i pi/4}
__device__ __forceinline__ float2 mulW48 (float2 a){return make_float2(CC*(a.y-a.x), -CC*(a.x+a.y));} // *e^{-3i pi/4}
__device__ __forceinline__ float2 mulW16c(float2 a){return make_float2(CC*(a.x-a.y),  CC*(a.x+a.y));} // *e^{+i pi/4}
__device__ __forceinline__ float2 mulW48c(float2 a){return make_float2(-CC*(a.x+a.y), CC*(a.x-a.y));} // *e^{+3i pi/4}
__device__ __forceinline__ int brev7(int k){return (int)(__brev((unsigned)k) >> 25);}

// Forward DIF radix-4 (fuses radix-2 stages s, s+1). w2 = w1*(-i), w3 = w1^2.
__device__ __forceinline__ void bf4f(float2& a0, float2& a1, float2& a2, float2& a3, float2 w1){
    float2 w2 = mul_mi(w1);
    float2 w3 = cmul(w1, w1);
    float2 b0 = cadd(a0, a2);
    float2 b2 = cmul(csub(a0, a2), w1);
    float2 b1 = cadd(a1, a3);
    float2 b3 = cmul(csub(a1, a3), w2);
    a0 = cadd(b0, b1);
    a1 = cmul(csub(b0, b1), w3);
    a2 = cadd(b2, b3);
    a3 = cmul(csub(b2, b3), w3);
}

// Inverse conj-DIT radix-4 (fuses radix-2 stages shift=t, t+1). cw1 = cw2^2, cw3 = i*cw2.
__device__ __forceinline__ void bf4i(float2& a0, float2& a1, float2& a2, float2& a3, float2 cw2){
    float2 cw1 = cmul(cw2, cw2);
    float2 cw3 = mul_pi(cw2);
    float2 t;
    t = cmul(a1, cw1); float2 b0 = cadd(a0, t), b1 = csub(a0, t);
    t = cmul(a3, cw1); float2 b2 = cadd(a2, t), b3 = csub(a2, t);
    t = cmul(b2, cw2); a0 = cadd(b0, t); a2 = csub(b0, t);
    t = cmul(b3, cw3); a1 = cadd(b1, t); a3 = csub(b1, t);
}

// Forward DIF radix-8 = radix-2 stages s=4,5,6 on 8 contiguous points. Constant twiddles.
__device__ __forceinline__ void bf8f(float2 x[8]){
    float2 y0=cadd(x[0],x[4]), y4=csub(x[0],x[4]);
    float2 y1=cadd(x[1],x[5]), y5=mulW16(csub(x[1],x[5]));
    float2 y2=cadd(x[2],x[6]), y6=mul_mi(csub(x[2],x[6]));
    float2 y3=cadd(x[3],x[7]), y7=mulW48(csub(x[3],x[7]));
    float2 z0=cadd(y0,y2), z2=csub(y0,y2);
    float2 z1=cadd(y1,y3), z3=mul_mi(csub(y1,y3));
    float2 z4=cadd(y4,y6), z6=csub(y4,y6);
    float2 z5=cadd(y5,y7), z7=mul_mi(csub(y5,y7));
    x[0]=cadd(z0,z1); x[1]=csub(z0,z1);
    x[2]=cadd(z2,z3); x[3]=csub(z2,z3);
    x[4]=cadd(z4,z5); x[5]=csub(z4,z5);
    x[6]=cadd(z6,z7); x[7]=csub(z6,z7);
}

// Inverse conj-DIT radix-8 = radix-2 stages shift=0,1,2 on 8 contiguous points.
__device__ __forceinline__ void bf8i(float2 x[8]){
    float2 y0=cadd(x[0],x[1]), y1=csub(x[0],x[1]);
    float2 y2=cadd(x[2],x[3]), y3=csub(x[2],x[3]);
    float2 y4=cadd(x[4],x[5]), y5=csub(x[4],x[5]);
    float2 y6=cadd(x[6],x[7]), y7=csub(x[6],x[7]);
    float2 t;
    float2 z0=cadd(y0,y2), z2=csub(y0,y2);
    t = mul_pi(y3);
    float2 z1=cadd(y1,t), z3=csub(y1,t);
    float2 z4=cadd(y4,y6), z6=csub(y4,y6);
    t = mul_pi(y7);
    float2 z5=cadd(y5,t), z7=csub(y5,t);
    x[0]=cadd(z0,z4); x[4]=csub(z0,z4);
    t = mulW16c(z5); x[1]=cadd(z1,t); x[5]=csub(z1,t);
    t = mul_pi(z6);  x[2]=cadd(z2,t); x[6]=csub(z2,t);
    t = mulW48c(z7); x[3]=cadd(z3,t); x[7]=csub(z3,t);
}

// ---------------- sweeps (each ends with __syncthreads) ----------------

// Generic forward radix-4 sweep over all 128 lines. S in {0,2}. ROWS: along x vs along y.
template<int S, bool ROWS>
__device__ __noinline__ void sweep_r4f(float2* F, const float2* TW){
    constexpr int q = 1 << (5 - S);
    #pragma unroll 2
    for (int b = threadIdx.x; b < 4096; b += NT) {
        int j = b >> 7, l = b & 127;
        int p0 = j & (q - 1);
        int i = ((j >> (5 - S)) << (7 - S)) + p0;
        int base = ROWS ? (l * LD + i) : (i * LD + l);
        int st   = ROWS ? q : q * LD;
        float2 a0 = F[base], a1 = F[base+st], a2 = F[base+2*st], a3 = F[base+3*st];
        bf4f(a0, a1, a2, a3, TW[p0 << S]);
        F[base] = a0; F[base+st] = a1; F[base+2*st] = a2; F[base+3*st] = a3;
    }
    __syncthreads();
}

// Forward radix-4 S=0 along rows, FUSED with pointwise multiply by obj patch
// (and by probe on the first round, reading the field from global instead of SMEM).
// Thread mapping (j = tid&31, l = tid>>5) keeps global loads coalesced and SMEM stride-1.
template<bool FIRST>
__device__ __noinline__ void sweep_r4f_rows0_fused(
    float2* F, const float2* TW,
    const float* __restrict__ obr, const float* __restrict__ obi, int obase,
    const float* __restrict__ prm, const float* __restrict__ pim)
{
    #pragma unroll 2
    for (int b = threadIdx.x; b < 4096; b += NT) {
        int j = b & 31, l = b >> 5;
        int rowS = l * LD;
        int rowG = obase + l * 512;
        float2 a[4];
        #pragma unroll
        for (int k = 0; k < 4; ++k) {
            int x = j + 32 * k;
            float2 T = make_float2(obr[rowG + x], obi[rowG + x]);
            float2 v;
            if (FIRST) v = make_float2(prm[(l << 7) + x], pim[(l << 7) + x]);
            else       v = F[rowS + x];
            a[k] = cmul(v, T);
        }
        bf4f(a[0], a[1], a[2], a[3], TW[j]);
        F[rowS + j] = a[0]; F[rowS + j + 32] = a[1];
        F[rowS + j + 64] = a[2]; F[rowS + j + 96] = a[3];
    }
    __syncthreads();
}

// Forward radix-8 sweep (stages 4,5,6). Optionally fuse propagator multiply on write
// (PF stored in bit-reversed index order, carries the 1/128-per-axis ifft scale).
template<bool ROWS, bool PROP>
__device__ __noinline__ void sweep_r8f(float2* F, const float2* PF){
    #pragma unroll 1
    for (int b = threadIdx.x; b < 2048; b += NT) {
        int g = b >> 7, l = b & 127;
        int i0 = g << 3;
        float2 x[8];
        #pragma unroll
        for (int k = 0; k < 8; ++k)
            x[k] = ROWS ? F[l * LD + i0 + k] : F[(i0 + k) * LD + l];
        bf8f(x);
        if (PROP) {
            float2 pl = PF[l];
            #pragma unroll
            for (int k = 0; k < 8; ++k)
                x[k] = cmul(x[k], cmul(PF[i0 + k], pl));
        }
        #pragma unroll
        for (int k = 0; k < 8; ++k)
            (ROWS ? F[l * LD + i0 + k] : F[(i0 + k) * LD + l]) = x[k];
    }
    __syncthreads();
}

// Inverse radix-8 sweep (stages shift=0,1,2) — first step of each inverse 1-D FFT.
template<bool ROWS>
__device__ __noinline__ void sweep_r8i(float2* F){
    #pragma unroll 1
    for (int b = threadIdx.x; b < 2048; b += NT) {
        int g = b >> 7, l = b & 127;
        int i0 = g << 3;
        float2 x[8];
        #pragma unroll
        for (int k = 0; k < 8; ++k)
            x[k] = ROWS ? F[l * LD + i0 + k] : F[(i0 + k) * LD + l];
        bf8i(x);
        #pragma unroll
        for (int k = 0; k < 8; ++k)
            (ROWS ? F[l * LD + i0 + k] : F[(i0 + k) * LD + l]) = x[k];
    }
    __syncthreads();
}

// Inverse radix-4 sweep (stages shift=T, T+1). T in {3,5}.
template<int T, bool ROWS>
__device__ __noinline__ void sweep_r4i(float2* F, const float2* TW){
    constexpr int h = 1 << T;
    #pragma unroll 2
    for (int b = threadIdx.x; b < 4096; b += NT) {
        int j = b >> 7, l = b & 127;
        int p0 = j & (h - 1);
        int i = ((j >> T) << (T + 2)) + p0;
        int base = ROWS ? (l * LD + i) : (i * LD + l);
        int st   = ROWS ? h : h * LD;
        float2 a0 = F[base], a1 = F[base+st], a2 = F[base+2*st], a3 = F[base+3*st];
        float2 w = TW[p0 << (5 - T)];
        bf4i(a0, a1, a2, a3, make_float2(w.x, -w.y));
        F[base] = a0; F[base+st] = a1; F[base+2*st] = a2; F[base+3*st] = a3;
    }
    __syncthreads();
}

__global__ void __launch_bounds__(NT, 1)
ms_kernel(const float* __restrict__ pr, const float* __restrict__ pim,
          const float* __restrict__ obr, const float* __restrict__ obi,
          const int* __restrict__ posn, float* __restrict__ out)
{
    extern __shared__ float2 sm[];
    float2* F  = sm;                  // [128][129] field
    float2* TW = sm + NPIX * LD;      // 64 forward twiddles W_128^k
    float2* PF = TW + 64;             // 128 propagator axis factors, bit-reversed, * (1/128)

    const int tid = threadIdx.x;
    const int n = blockIdx.x >> 2;    // scan position
    const int m = blockIdx.x & 3;     // probe mode
    const int py0 = posn[2 * n];
    const int px0 = posn[2 * n + 1];

    // --- tables ---
    if (tid < 64) {
        float ang = -2.0f * PI_F * (float)tid * (1.0f / 128.0f);
        float sv, cv; sincosf(ang, &sv, &cv);
        TW[tid] = make_float2(cv, sv);
    } else if (tid < 192) {
        int k = tid - 64;
        int kk = brev7(k);
        float f = (float)(kk < 64 ? kk : kk - 128) * (1.0f / (128.0f * 0.2f)); // fftfreq
        float phase = -PI_F * 0.025f * 2.0f * f * f;   // -pi*wl*dz*k^2 per axis
        float sv, cv; sincosf(phase, &sv, &cv);
        PF[k] = make_float2(cv * (1.0f / 128.0f), sv * (1.0f / 128.0f)); // fold ifft scale
    }
    __syncthreads();

    const float* prm = pr  + m * (NPIX * NPIX);
    const float* pmm = pim + m * (NPIX * NPIX);

    // 8 rounds: [*patch_s (fused)] fft2 ; rounds 0..6 additionally: [*prop (fused)] ifft2
    #pragma unroll 1
    for (int s = 0; s < 8; ++s) {
        const int obase = ((s << 9) + py0) * 512 + px0;   // slice s patch origin

        // forward rows: 3 sweeps (first fused with patch/probe multiply)
        if (s == 0) sweep_r4f_rows0_fused<true >(F, TW, obr, obi, obase, prm, pmm);
        else        sweep_r4f_rows0_fused<false>(F, TW, obr, obi, obase, prm, pmm);
        sweep_r4f<2, true>(F, TW);
        sweep_r8f<true, false>(F, PF);

        // forward cols: 3 sweeps (last fused with propagator, except final round)
        sweep_r4f<0, false>(F, TW);
        sweep_r4f<2, false>(F, TW);
        if (s < 7) {
            sweep_r8f<false, true>(F, PF);
            // inverse cols then inverse rows: 3 + 3 sweeps
            sweep_r8i<false>(F);
            sweep_r4i<3, false>(F, TW);
            sweep_r4i<5, false>(F, TW);
            sweep_r8i<true>(F);
            sweep_r4i<3, true>(F, TW);
            sweep_r4i<5, true>(F, TW);
        } else {
            sweep_r8f<false, false>(F, PF);
        }
    }

    // out[n,y,x] += |X[(y+64)%128][(x+64)%128]|^2 with X[k] at F[brev7(k)]
    float* outn = out + n * (NPIX * NPIX);
    for (int e = tid; e < NPIX * NPIX; e += NT) {
        int y = e >> 7, x = e & 127;
        int u = brev7((y + 64) & 127);
        int v = brev7((x + 64) & 127);
        float2 a = F[u * LD + v];
        atomicAdd(&outn[e], fmaf(a.x, a.x, a.y * a.y));
    }
}

extern "C" void kernel_launch(void* const* d_in, const int* in_sizes, int n_in,
                              void* d_out, int out_size)
{
    const float* pr  = (const float*)d_in[0];  // probe_real (4,128,128)
    const float* pim = (const float*)d_in[1];  // probe_imag
    const float* obr = (const float*)d_in[2];  // obj_real   (8,512,512)
    const float* obi = (const float*)d_in[3];  // obj_imag
    const int*   pos = (const int*)d_in[4];    // positions  (512,2)
    float* out = (float*)d_out;                // (512,128,128) float32

    cudaMemsetAsync(out, 0, (size_t)out_size * sizeof(float), 0);

    size_t smem = (size_t)(NPIX * LD + 64 + NPIX) * sizeof(float2);  // 133,632 B
    cudaFuncSetAttribute(ms_kernel, cudaFuncAttributeMaxDynamicSharedMemorySize, (int)smem);
    ms_kernel<<<512 * 4, NT, smem>>>(pr, pim, obr, obi, pos, out);
}